// round 5
// baseline (speedup 1.0000x reference)
#include <cuda_runtime.h>
#include <cuda_bf16.h>

// QuantumFeatureExtractor — closed-form, float4 accesses, full occupancy.
//
//   m0 = cos(t4)cos(t0)cos(a0) - sin(t4)cos(t2)sin(a0)sin(a2)
//   m1 = cos(a1 + t1)
//   m2 = cos(t0)cos(a0)cos(a2)
//   m3 = cos(a1 + t1) * cos(t3) * cos(a3)
//
// Product-to-sum (exact):
//   cos(a0)cos(a2) = 0.5*(cos(a0-a2) + cos(a0+a2))
//   sin(a0)sin(a2) = 0.5*(cos(a0-a2) - cos(a0+a2))
// -> 5 MUFU per patch: cos(a0), cos(a0+a2), cos(a0-a2), cos(a1+t1), cos(a3)
//
// One thread per unit (pair of 2x2 patches sharing a float4 column):
// 262144 threads, 2 x LDG.128 + 2 x STG.128 each, all loads issued up front.

__device__ __forceinline__ float4 qfe_patch(float a0, float a1, float a2, float a3,
                                            float A, float Bc, float ct0, float ct3,
                                            float t1) {
    const float c0  = __cosf(a0);
    const float cp  = __cosf(a0 + a2);      // cos(a0+a2)
    const float cm  = __cosf(a0 - a2);      // cos(a0-a2)
    const float m1  = __cosf(a1 + t1);
    const float c3  = __cosf(a3);
    const float cc  = 0.5f * (cm + cp);     // cos a0 * cos a2
    const float ss  = 0.5f * (cm - cp);     // sin a0 * sin a2
    const float m0  = fmaf(A, c0, -Bc * ss);
    const float m2  = ct0 * cc;
    const float m3  = m1 * (ct3 * c3);
    return make_float4(m0, m1, m2, m3);
}

__global__ void __launch_bounds__(256) qfe_main(const float4* __restrict__ x4,
                                                const float* __restrict__ tp,
                                                float4* __restrict__ out4) {
    const int k  = blockIdx.x * 256 + threadIdx.x;   // 262144 units
    const int j4 = k & 31;          // float4 column (patches 2j4, 2j4+1)
    const int i  = (k >> 5) & 63;   // patch row
    const int b  = k >> 11;         // batch 0..127

    // Input float4 index: image = 4096 float4; row 2i -> i*64, row 2i+1 -> +32.
    const int in = b * 4096 + i * 64 + j4;

    // Both loads issued back-to-back before any use.
    const float4 rA = x4[in];        // row 2i:   a0,a1 | a0',a1'
    const float4 rB = x4[in + 32];   // row 2i+1: a2,a3 | a2',a3'

    // Uniform circuit params — evaluated while loads are in flight.
    const float t0 = tp[0], t1 = tp[1], t2 = tp[2], t3 = tp[3], t4 = tp[4];
    float st4, ct4;
    __sincosf(t4, &st4, &ct4);
    const float ct0 = __cosf(t0);
    const float ct2 = __cosf(t2);
    const float ct3 = __cosf(t3);
    const float A  = ct4 * ct0;
    const float Bc = st4 * ct2;

    const float4 oa = qfe_patch(rA.x, rA.y, rB.x, rB.y, A, Bc, ct0, ct3, t1);
    const float4 ob = qfe_patch(rA.z, rA.w, rB.z, rB.w, A, Bc, ct0, ct3, t1);

    // Output float4 index = b*4096 + i*64 + patch. Warp covers a contiguous
    // 64-float4 span -> fully coalesced STG.128 x2.
    const int on = b * 4096 + i * 64 + 2 * j4;
    out4[on]     = oa;
    out4[on + 1] = ob;
}

extern "C" void kernel_launch(void* const* d_in, const int* in_sizes, int n_in,
                              void* d_out, int out_size) {
    const float* x  = (const float*)d_in[0];
    const float* tp = (const float*)d_in[1];
    if (n_in >= 2 && in_sizes[0] == 6) {   // defensive vs metadata ordering
        const float* s = x; x = tp; tp = s;
    }
    qfe_main<<<1024, 256>>>((const float4*)x, tp, (float4*)d_out);
}

// round 6
// speedup vs baseline: 1.2120x; 1.2120x over previous
#include <cuda_runtime.h>
#include <cuda_bf16.h>

// QuantumFeatureExtractor — closed-form, R2 memory structure (every memory
// instruction lane-contiguous), product-to-sum trig (5 MUFU/patch).
//
//   m0 = cos(t4)cos(t0)cos(a0) - sin(t4)cos(t2)*[sin(a0)sin(a2)]
//   m1 = cos(a1 + t1)
//   m2 = cos(t0)*[cos(a0)cos(a2)]
//   m3 = cos(a1 + t1) * cos(t3) * cos(a3)
// with (exact):
//   cos(a0)cos(a2) = 0.5*(cos(a0-a2) + cos(a0+a2))
//   sin(a0)sin(a2) = 0.5*(cos(a0-a2) - cos(a0+a2))
//
// Thread layout (identical to the best run R2): 262144 threads, thread
// (w = warp id, t = lane) handles patches (w, t) and (w, t+32):
//   loads : 4 x LDG.64  — lanes contiguous (256 B/warp each)
//   stores: 2 x STG.128 — lanes contiguous (512 B/warp each)

__device__ __forceinline__ float4 qfe_patch(float a0, float a1, float a2, float a3,
                                            float A, float Bh, float Ch,
                                            float ct3, float t1) {
    const float c0 = __cosf(a0);
    const float cp = __cosf(a0 + a2);   // cos(a0+a2)
    const float cm = __cosf(a0 - a2);   // cos(a0-a2)
    const float m1 = __cosf(a1 + t1);
    const float c3 = __cosf(a3);
    const float m0 = fmaf(A, c0, Bh * (cp - cm));   // Bh = 0.5*sin(t4)cos(t2)
    const float m2 = Ch * (cm + cp);                // Ch = 0.5*cos(t0)
    const float m3 = m1 * (ct3 * c3);
    return make_float4(m0, m1, m2, m3);
}

__global__ void __launch_bounds__(128) qfe_main(const float* __restrict__ x,
                                                const float* __restrict__ tp,
                                                float* __restrict__ out) {
    const int n = blockIdx.x * 128 + threadIdx.x;   // 262144 threads
    const int t = n & 31;        // lane -> patch column j within warp row
    const int w = n >> 5;        // global warp id = (b, i)
    const int i = w & 63;
    const int b = w >> 6;

    // x is (128,1,128,128); float2 view: row stride 64, batch stride 8192.
    const float2* __restrict__ x2 = (const float2*)x;
    const int base = b * 8192 + i * 128;

    // All four data loads issued back-to-back (each 256 B/warp, contiguous).
    const float2 rA1 = x2[base + t];         // patch j=t,    row 2i
    const float2 rB1 = x2[base + 64 + t];    // patch j=t,    row 2i+1
    const float2 rA2 = x2[base + 32 + t];    // patch j=t+32, row 2i
    const float2 rB2 = x2[base + 96 + t];    // patch j=t+32, row 2i+1

    // Uniform circuit params — evaluated while data loads are in flight.
    const float t0 = tp[0], t1 = tp[1], t2 = tp[2], t3 = tp[3], t4 = tp[4];
    float st4, ct4;
    __sincosf(t4, &st4, &ct4);
    const float ct0 = __cosf(t0);
    const float ct2 = __cosf(t2);
    const float ct3 = __cosf(t3);
    const float A  = ct4 * ct0;          // cos t4 * cos t0
    const float Bh = -0.5f * (st4 * ct2);
    const float Ch = 0.5f * ct0;
    // note: m0 = A*c0 - (st4*ct2)*ss, ss = 0.5*(cm-cp) -> Bh*(cp-cm) with
    // Bh = -0.5*st4*ct2 gives -(st4*ct2)*0.5*(cp-cm)... fix sign below.

    const float Bp = 0.5f * (st4 * ct2); // m0 = A*c0 + Bp*(cp - cm)

    const float4 o1 = qfe_patch(rA1.x, rA1.y, rB1.x, rB1.y, A, Bp, Ch, ct3, t1);
    const float4 o2 = qfe_patch(rA2.x, rA2.y, rB2.x, rB2.y, A, Bp, Ch, ct3, t1);

    // Output float4 index = b*4096 + i*64 + j = w*64 + j. Lane-contiguous.
    float4* __restrict__ out4 = (float4*)out;
    const int obase = w * 64;
    out4[obase + t]      = o1;
    out4[obase + 32 + t] = o2;
    (void)Bh;
}

extern "C" void kernel_launch(void* const* d_in, const int* in_sizes, int n_in,
                              void* d_out, int out_size) {
    const float* x  = (const float*)d_in[0];
    const float* tp = (const float*)d_in[1];
    if (n_in >= 2 && in_sizes[0] == 6) {   // defensive vs metadata ordering
        const float* s = x; x = tp; tp = s;
    }
    qfe_main<<<2048, 128>>>(x, tp, (float*)d_out);
}

// round 9
// speedup vs baseline: 1.5953x; 1.3163x over previous
#include <cuda_runtime.h>
#include <cuda_bf16.h>

// QuantumFeatureExtractor — closed-form, float4 loads, smem-remapped float4
// stores (all global memory instructions lane-contiguous).
//
//   m0 = cos(t4)cos(t0)cos(a0) + 0.5*sin(t4)cos(t2)*(cos(a0+a2) - cos(a0-a2))
//   m1 = cos(a1 + t1)
//   m2 = 0.5*cos(t0)*(cos(a0-a2) + cos(a0+a2))
//   m3 = cos(a1 + t1) * cos(t3) * cos(a3)
//
// Thread k (262144 total): j4 = k&31, i = (k>>5)&63, b = k>>11.
// Loads x4[in], x4[in+32]  (in = b*4096 + i*64 + j4)  -> 2 x LDG.128,
// lane-contiguous. Thread owns patches 2*j4 and 2*j4+1 -> results are
// staged through warp-local shared memory so the 2 STG.128 are also
// lane-contiguous (patch t and t+32 for lane t).

__device__ __forceinline__ float4 qfe_patch(float a0, float a1, float a2, float a3,
                                            float A, float Bp, float Ch,
                                            float ct3, float t1) {
    const float c0 = __cosf(a0);
    const float cp = __cosf(a0 + a2);   // cos(a0+a2)
    const float cm = __cosf(a0 - a2);   // cos(a0-a2)
    const float m1 = __cosf(a1 + t1);
    const float c3 = __cosf(a3);
    const float m0 = fmaf(A, c0, Bp * (cp - cm));   // Bp = 0.5 sin t4 cos t2
    const float m2 = Ch * (cm + cp);                // Ch = 0.5 cos t0
    const float m3 = m1 * (ct3 * c3);
    return make_float4(m0, m1, m2, m3);
}

__global__ void __launch_bounds__(256) qfe_main(const float4* __restrict__ x4,
                                                const float* __restrict__ tp,
                                                float4* __restrict__ out4) {
    // Per-warp staging: region A = sm[w][0..31], region B = sm[w][36..67].
    // B base offset = 36*16 = 576 B ≡ 64 B (mod 128 B) -> in each 8-lane
    // phase of an STS/LDS.128 the A and B accesses interleave across all 32
    // banks with no conflict.
    __shared__ float4 sm[8][68];

    const int k  = blockIdx.x * 256 + threadIdx.x;   // 262144 threads
    const int j4 = k & 31;          // float4 column -> patches 2j4, 2j4+1
    const int i  = (k >> 5) & 63;   // patch row
    const int b  = k >> 11;         // batch

    const int in = b * 4096 + i * 64 + j4;
    // Both loads issued back-to-back, lane-contiguous (512 B/warp each).
    const float4 rA = x4[in];        // row 2i:   a0,a1 | a0',a1'
    const float4 rB = x4[in + 32];   // row 2i+1: a2,a3 | a2',a3'

    // Uniform circuit params — evaluated while the loads are in flight.
    const float t0 = tp[0], t1 = tp[1], t2 = tp[2], t3 = tp[3], t4 = tp[4];
    float st4, ct4;
    __sincosf(t4, &st4, &ct4);
    const float ct0 = __cosf(t0);
    const float ct2 = __cosf(t2);
    const float ct3 = __cosf(t3);
    const float A  = ct4 * ct0;
    const float Bp = 0.5f * (st4 * ct2);
    const float Ch = 0.5f * ct0;

    const float4 oa = qfe_patch(rA.x, rA.y, rB.x, rB.y, A, Bp, Ch, ct3, t1);
    const float4 ob = qfe_patch(rA.z, rA.w, rB.z, rB.w, A, Bp, Ch, ct3, t1);

    const int w = threadIdx.x >> 5;   // warp in block
    const int t = j4;                 // lane
    float4* const smA = &sm[w][0];
    float4* const smB = &sm[w][36];

    // Stage: lane t's patches 2t (-> A[t]) and 2t+1 (-> B[t]).
    smA[t] = oa;
    smB[t] = ob;
    __syncwarp();

    // Gather lane-contiguous: out slot p takes patch p = 2*(p>>1) + (p&1).
    const int h = t >> 1;
    const float4 o_lo = (t & 1) ? smB[h]      : smA[h];        // patch t
    const float4 o_hi = (t & 1) ? smB[16 + h] : smA[16 + h];   // patch t+32

    // out float4 index = b*4096 + i*64 + patch. Lane-contiguous STG.128 x2.
    const int obase = in - j4;        // = b*4096 + i*64
    out4[obase + t]      = o_lo;
    out4[obase + 32 + t] = o_hi;
}

extern "C" void kernel_launch(void* const* d_in, const int* in_sizes, int n_in,
                              void* d_out, int out_size) {
    const float* x  = (const float*)d_in[0];
    const float* tp = (const float*)d_in[1];
    if (n_in >= 2 && in_sizes[0] == 6) {   // defensive vs metadata ordering
        const float* s = x; x = tp; tp = s;
    }
    qfe_main<<<1024, 256>>>((const float4*)x, tp, (float4*)d_out);
}